// round 2
// baseline (speedup 1.0000x reference)
#include <cuda_runtime.h>
#include <math.h>

#define NB 16
#define NT 100
#define NW 132
#define HID 100
#define FEAT 17424   /* 132*132 */

typedef unsigned long long ull;

// ---------------- static scratch (no runtime allocation allowed) ----------
__device__ float g_xT[(size_t)NB * NW * NT * 159];   // [b][w][i][h]
__device__ float g_c3[(size_t)NB * NW * NT * 132];   // [b][w][t][h]
__device__ float g_gi[(size_t)NB * NT * FEAT];       // [b][t][feat]
__device__ float g_wa[100 * 100 * 19];               // W2∘W1  [p][i][k]
__device__ float g_wc[28 * 100 * 100];               // W3∘W2∘W1 [k][i][o]
__device__ float g_s2[100];
__device__ float g_bc[100];
__device__ float g_xw[(size_t)NB * NT * 300];        // GRU input proj
__device__ float g_h [(size_t)NB * NT * HID];        // GRU outputs

// ---------------- f32x2 helpers ---------------------------------------------
__device__ __forceinline__ ull fma2(ull a, ull b, ull c) {
    ull d;
    asm("fma.rn.f32x2 %0, %1, %2, %3;" : "=l"(d) : "l"(a), "l"(b), "l"(c));
    return d;
}
__device__ __forceinline__ ull packf2(float x, float y) {
    ull d;
    asm("mov.b64 %0, {%1, %2};" : "=l"(d) : "f"(x), "f"(y));
    return d;
}
__device__ __forceinline__ float2 unpackf2(ull v) {
    float2 r;
    asm("mov.b64 {%0, %1}, %2;" : "=f"(r.x), "=f"(r.y) : "l"(v));
    return r;
}
__device__ __forceinline__ float f2lo(ull v) {
    float x, y;
    asm("mov.b64 {%0, %1}, %2;" : "=f"(x), "=f"(y) : "l"(v));
    return x;
}
__device__ __forceinline__ float f2hi(ull v) {
    float x, y;
    asm("mov.b64 {%0, %1}, %2;" : "=f"(x), "=f"(y) : "l"(v));
    return y;
}

// ---------------- weight composition ----------------------------------------
// Wa[p,i,k] = sum_{k1+k2=k} sum_m W2[p,m,k2] * W1[m,i,k1]      k in [0,19)
__global__ void compose1_k(const float* __restrict__ w2, const float* __restrict__ w1)
{
    int idx = blockIdx.x * blockDim.x + threadIdx.x;
    if (idx >= 100 * 100 * 19) return;
    int p = idx / (100 * 19);
    int i = (idx / 19) % 100;
    int kap = idx % 19;
    int k1lo = kap - 9 > 0 ? kap - 9 : 0;
    int k1hi = kap < 9 ? kap : 9;
    float acc = 0.f;
    for (int m = 0; m < 100; m++) {
        const float* w2r = w2 + (p * 100 + m) * 10;
        const float* w1r = w1 + (m * 100 + i) * 10;
        for (int k1 = k1lo; k1 <= k1hi; k1++)
            acc += w2r[kap - k1] * w1r[k1];
    }
    g_wa[(p * 100 + i) * 19 + kap] = acc;
}

// Wc[o,i,k] = sum_{k3+k1=k} sum_m W3[o,m,k3] * Wa[m,i,k1]      k in [0,28)
// stored as [k][i][o]
__global__ void compose2_k(const float* __restrict__ w3)
{
    int idx = blockIdx.x * blockDim.x + threadIdx.x;
    if (idx >= 100 * 100 * 28) return;
    int o = idx / (100 * 28);
    int i = (idx / 28) % 100;
    int kap = idx % 28;
    int k3lo = kap - 18 > 0 ? kap - 18 : 0;
    int k3hi = kap < 9 ? kap : 9;
    float acc = 0.f;
    for (int m = 0; m < 100; m++) {
        const float* w3r = w3 + (o * 100 + m) * 10;
        const float* war = g_wa + (m * 100 + i) * 19;
        for (int k3 = k3lo; k3 <= k3hi; k3++)
            acc += w3r[k3] * war[kap - k3];
    }
    g_wc[(kap * 100 + i) * 100 + o] = acc;
}

// bias composition
__global__ void bias1_k(const float* __restrict__ w2, const float* __restrict__ b1,
                        const float* __restrict__ b2)
{
    int t = threadIdx.x;
    if (t >= 100) return;
    float s = b2[t];
    for (int m = 0; m < 100; m++) {
        const float* r = w2 + (t * 100 + m) * 10;
        float ws = 0.f;
#pragma unroll
        for (int k = 0; k < 10; k++) ws += r[k];
        s += ws * b1[m];
    }
    g_s2[t] = s;
}
__global__ void bias2_k(const float* __restrict__ w3, const float* __restrict__ b3)
{
    int t = threadIdx.x;
    if (t >= 100) return;
    float s = b3[t];
    for (int m = 0; m < 100; m++) {
        const float* r = w3 + (t * 100 + m) * 10;
        float ws = 0.f;
#pragma unroll
        for (int k = 0; k < 10; k++) ws += r[k];
        s += ws * g_s2[m];
    }
    g_bc[t] = s;
}

// ---------------- x: [b][i][h][w] -> [b][w][i][h] --------------------------
__global__ void transpose_x_k(const float* __restrict__ x)
{
    __shared__ float s[32][33];
    int plane = blockIdx.x;               // b*100 + i
    int b = plane / 100, i = plane % 100;
    int h0 = blockIdx.y * 32, w0 = blockIdx.z * 32;
    int tx = threadIdx.x, ty = threadIdx.y;
    const float* xp = x + (size_t)plane * (159 * 132);
#pragma unroll
    for (int j = 0; j < 4; j++) {
        int h = h0 + ty + j * 8, w = w0 + tx;
        if (h < 159 && w < 132) s[ty + j * 8][tx] = xp[h * 132 + w];
    }
    __syncthreads();
#pragma unroll
    for (int j = 0; j < 4; j++) {
        int w = w0 + ty + j * 8, h = h0 + tx;
        if (w < 132 && h < 159)
            g_xT[((size_t)(b * 132 + w) * 100 + i) * 159 + h] = s[tx][ty + j * 8];
    }
}

// ---------------- fused composite conv (K=2800), FFMA2 ----------------------
// in : g_xT [b][w][i][159]  -> smem slab padded to 168/row (zero tail)
// wt : g_wc [k][i][o]       (L2 resident, 1.12MB)
// out: g_c3 [b][w][o][132]
__global__ void __launch_bounds__(512, 1)
convc_k()
{
    extern __shared__ float xs[];        // 100 * 168
    const int bw = blockIdx.x;           // b*132 + w
    const float* inp = g_xT + (size_t)bw * (100 * 159);
    float* outp = g_c3 + (size_t)bw * (100 * 132);
    const int tid = threadIdx.x;

    for (int idx = tid; idx < 100 * 168; idx += 512) {
        int i = idx / 168, h = idx - i * 168;
        xs[idx] = (h < 159) ? inp[i * 159 + h] : 0.f;
    }
    __syncthreads();

    const int og = tid % 50;             // 50 groups of 2 output channels
    const int hg = tid / 50;             // 10 h-groups of 14 outputs
    if (hg >= 10) return;
    const int h0 = hg * 14;
    const int ob = og * 2;

    ull acc0[7], acc1[7];
#pragma unroll
    for (int m = 0; m < 7; m++) { acc0[m] = 0ull; acc1[m] = 0ull; }

    for (int i = 0; i < 100; i++) {
        const float* xrow = xs + i * 168 + h0;
        ull ev[21];
#pragma unroll
        for (int j = 0; j < 21; j++)
            ev[j] = *(const ull*)(xrow + 2 * j);   // 8B aligned: 168*i even, h0 even

        const float* wbase = g_wc + i * 100 + ob;
        // even taps: pair {x[h0+kk+2m], x[h0+kk+2m+1]} = ev[kk/2+m]
#pragma unroll
        for (int kk = 0; kk < 28; kk += 2) {
            float2 w = *(const float2*)(wbase + (size_t)kk * 10000);
            ull w0 = packf2(w.x, w.x);
            ull w1 = packf2(w.y, w.y);
            const int s0 = kk >> 1;
#pragma unroll
            for (int m = 0; m < 7; m++) {
                ull xv = ev[s0 + m];
                acc0[m] = fma2(xv, w0, acc0[m]);
                acc1[m] = fma2(xv, w1, acc1[m]);
            }
        }
        // build odd-aligned pairs in place: ev[j] := {ev[j].hi, ev[j+1].lo}
#pragma unroll
        for (int j = 0; j < 20; j++)
            ev[j] = packf2(f2hi(ev[j]), f2lo(ev[j + 1]));
        // odd taps: pair = od[(kk-1)/2 + m]
#pragma unroll
        for (int kk = 1; kk < 28; kk += 2) {
            float2 w = *(const float2*)(wbase + (size_t)kk * 10000);
            ull w0 = packf2(w.x, w.x);
            ull w1 = packf2(w.y, w.y);
            const int s0 = (kk - 1) >> 1;
#pragma unroll
            for (int m = 0; m < 7; m++) {
                ull xv = ev[s0 + m];
                acc0[m] = fma2(xv, w0, acc0[m]);
                acc1[m] = fma2(xv, w1, acc1[m]);
            }
        }
    }

    float b0 = g_bc[ob], b1 = g_bc[ob + 1];
#pragma unroll
    for (int m = 0; m < 7; m++) {
        int h = h0 + 2 * m;
        float2 a0 = unpackf2(acc0[m]);
        float2 a1 = unpackf2(acc1[m]);
        if (h < 132) {
            outp[(ob + 0) * 132 + h] = a0.x + b0;
            outp[(ob + 1) * 132 + h] = a1.x + b1;
        }
        if (h + 1 < 132) {
            outp[(ob + 0) * 132 + h + 1] = a0.y + b0;
            outp[(ob + 1) * 132 + h + 1] = a1.y + b1;
        }
    }
}

// ---------------- c3: [b][w][t][h] -> gi [b][t][h*132+w] -------------------
__global__ void transpose_c_k()
{
    __shared__ float s[32][33];
    int plane = blockIdx.x;               // b*100 + t
    int b = plane / 100, t = plane % 100;
    int h0 = blockIdx.y * 32, w0 = blockIdx.z * 32;
    int tx = threadIdx.x, ty = threadIdx.y;
#pragma unroll
    for (int j = 0; j < 4; j++) {
        int w = w0 + ty + j * 8, h = h0 + tx;
        if (w < 132 && h < 132)
            s[ty + j * 8][tx] = g_c3[((size_t)(b * 132 + w) * 100 + t) * 132 + h];
    }
    __syncthreads();
#pragma unroll
    for (int j = 0; j < 4; j++) {
        int h = h0 + ty + j * 8, w = w0 + tx;
        if (h < 132 && w < 132)
            g_gi[(size_t)plane * FEAT + h * 132 + w] = s[tx][ty + j * 8];
    }
}

// ---------------- GRU input projection: xw = gi @ w_ih^T -------------------
// C[1600,300] = A[1600,17424] * B[300,17424]^T
__global__ void gemm_xw_k(const float* __restrict__ Bm)
{
    __shared__ float As[16][64];
    __shared__ float Bs[16][64];
    const int m0 = blockIdx.x * 64, n0 = blockIdx.y * 64;
    const int tid = threadIdx.x;
    const int tx = tid & 15, ty = tid >> 4;
    const int lrow = tid >> 2, lk = (tid & 3) << 2;

    ull acc01[4], acc23[4];
#pragma unroll
    for (int a = 0; a < 4; a++) { acc01[a] = 0ull; acc23[a] = 0ull; }

    const float* aptr = g_gi + (size_t)(m0 + lrow) * FEAT + lk;
    const int nn = n0 + lrow;
    const float* bptr = Bm + (size_t)(nn < 300 ? nn : 0) * FEAT + lk;

    for (int k0 = 0; k0 < FEAT; k0 += 16) {
        float4 av = *(const float4*)(aptr + k0);
        float4 bv = make_float4(0.f, 0.f, 0.f, 0.f);
        if (nn < 300) bv = *(const float4*)(bptr + k0);
        __syncthreads();
        As[lk + 0][lrow] = av.x; As[lk + 1][lrow] = av.y;
        As[lk + 2][lrow] = av.z; As[lk + 3][lrow] = av.w;
        Bs[lk + 0][lrow] = bv.x; Bs[lk + 1][lrow] = bv.y;
        Bs[lk + 2][lrow] = bv.z; Bs[lk + 3][lrow] = bv.w;
        __syncthreads();
#pragma unroll
        for (int kk = 0; kk < 16; kk++) {
            float4 a = *(const float4*)&As[kk][ty << 2];
            ull b01 = *(const ull*)&Bs[kk][tx << 2];
            ull b23 = *(const ull*)(&Bs[kk][(tx << 2) + 2]);
            ull a0 = packf2(a.x, a.x), a1 = packf2(a.y, a.y);
            ull a2 = packf2(a.z, a.z), a3 = packf2(a.w, a.w);
            acc01[0] = fma2(a0, b01, acc01[0]); acc23[0] = fma2(a0, b23, acc23[0]);
            acc01[1] = fma2(a1, b01, acc01[1]); acc23[1] = fma2(a1, b23, acc23[1]);
            acc01[2] = fma2(a2, b01, acc01[2]); acc23[2] = fma2(a2, b23, acc23[2]);
            acc01[3] = fma2(a3, b01, acc01[3]); acc23[3] = fma2(a3, b23, acc23[3]);
        }
    }
#pragma unroll
    for (int ii = 0; ii < 4; ii++) {
        int m = m0 + (ty << 2) + ii;
        float2 c01 = unpackf2(acc01[ii]);
        float2 c23 = unpackf2(acc23[ii]);
        int n = n0 + (tx << 2);
        float* op = g_xw + (size_t)m * 300;
        if (n + 0 < 300) op[n + 0] = c01.x;
        if (n + 1 < 300) op[n + 1] = c01.y;
        if (n + 2 < 300) op[n + 2] = c23.x;
        if (n + 3 < 300) op[n + 3] = c23.y;
    }
}

// ---------------- GRU recurrence: one block per batch element --------------
__global__ void __launch_bounds__(320)
gru_k(const float* __restrict__ w_hh, const float* __restrict__ b_ih,
      const float* __restrict__ b_hh)
{
    const int b = blockIdx.x;
    const int g = threadIdx.x;           // 0..319, 300 gate rows active
    __shared__ float h_s[104];
    __shared__ float gh_s[300];
    __shared__ float xw_s[300];

    float wreg[100];
    float bih = 0.f, bhh = 0.f;
    if (g < 300) {
        bih = b_ih[g];
        bhh = b_hh[g];
#pragma unroll
        for (int j = 0; j < 100; j++) wreg[j] = w_hh[g * 100 + j];
    }
    if (g < 104) h_s[g] = 0.f;
    __syncthreads();

    const float* xwp = g_xw + (size_t)b * 100 * 300;
    for (int t = 0; t < 100; t++) {
        if (g < 300) {
            float xv = xwp[t * 300 + g] + bih;
            float acc = bhh;
#pragma unroll
            for (int j4 = 0; j4 < 25; j4++) {
                float4 hv = *(const float4*)&h_s[j4 * 4];
                acc += wreg[j4 * 4 + 0] * hv.x;
                acc += wreg[j4 * 4 + 1] * hv.y;
                acc += wreg[j4 * 4 + 2] * hv.z;
                acc += wreg[j4 * 4 + 3] * hv.w;
            }
            gh_s[g] = acc;
            xw_s[g] = xv;
        }
        __syncthreads();
        if (g < 100) {
            float r = 1.f / (1.f + expf(-(xw_s[g] + gh_s[g])));
            float z = 1.f / (1.f + expf(-(xw_s[100 + g] + gh_s[100 + g])));
            float n = tanhf(xw_s[200 + g] + r * gh_s[200 + g]);
            float hn = (1.f - z) * n + z * h_s[g];
            h_s[g] = hn;
            g_h[((size_t)b * 100 + t) * 100 + g] = hn;
        }
        __syncthreads();
    }
}

// ---------------- output heads ---------------------------------------------
__global__ void heads_k(const float* __restrict__ wy1, const float* __restrict__ by1,
                        const float* __restrict__ wy2, const float* __restrict__ by2,
                        float* __restrict__ out)
{
    int idx = blockIdx.x * blockDim.x + threadIdx.x;
    if (idx >= 1600 * 17) return;
    int bt = idx / 17, c = idx - bt * 17;
    const float* gv = g_h + (size_t)bt * 100;
    if (c < 14) {
        const float* wv = wy1 + c * 100;
        float acc = by1[c];
#pragma unroll 4
        for (int j = 0; j < 100; j++) acc += gv[j] * wv[j];
        out[bt * 14 + c] = 1.f / (1.f + expf(-acc));
    } else {
        int c2 = c - 14;
        const float* wv = wy2 + c2 * 100;
        float acc = by2[c2];
#pragma unroll 4
        for (int j = 0; j < 100; j++) acc += gv[j] * wv[j];
        out[1600 * 14 + bt * 3 + c2] = tanhf(acc) * 10.f;
    }
}

// ---------------- launch ----------------------------------------------------
extern "C" void kernel_launch(void* const* d_in, const int* in_sizes, int n_in,
                              void* d_out, int out_size)
{
    (void)in_sizes; (void)n_in; (void)out_size;
    const float* x    = (const float*)d_in[0];
    const float* w1   = (const float*)d_in[1];
    const float* bc1  = (const float*)d_in[2];
    const float* w2   = (const float*)d_in[3];
    const float* bc2  = (const float*)d_in[4];
    const float* w3   = (const float*)d_in[5];
    const float* bc3  = (const float*)d_in[6];
    const float* w_ih = (const float*)d_in[7];
    const float* w_hh = (const float*)d_in[8];
    const float* b_ih = (const float*)d_in[9];
    const float* b_hh = (const float*)d_in[10];
    const float* w_y1 = (const float*)d_in[11];
    const float* b_y1 = (const float*)d_in[12];
    const float* w_y2 = (const float*)d_in[13];
    const float* b_y2 = (const float*)d_in[14];
    float* out = (float*)d_out;

    const int conv_smem = 100 * 168 * 4;
    cudaFuncSetAttribute(convc_k, cudaFuncAttributeMaxDynamicSharedMemorySize, conv_smem);

    compose1_k<<<(100 * 100 * 19 + 255) / 256, 256>>>(w2, w1);
    compose2_k<<<(100 * 100 * 28 + 255) / 256, 256>>>(w3);
    bias1_k<<<1, 128>>>(w2, bc1, bc2);
    bias2_k<<<1, 128>>>(w3, bc3);
    transpose_x_k<<<dim3(1600, 5, 5), dim3(32, 8)>>>(x);
    convc_k<<<NB * NW, 512, conv_smem>>>();
    transpose_c_k<<<dim3(1600, 5, 5), dim3(32, 8)>>>();
    gemm_xw_k<<<dim3(25, 5), 256>>>(w_ih);
    gru_k<<<16, 320>>>(w_hh, b_ih, b_hh);
    heads_k<<<(1600 * 17 + 255) / 256, 256>>>(w_y1, b_y1, w_y2, b_y2, out);
}

// round 3
// speedup vs baseline: 1.5642x; 1.5642x over previous
#include <cuda_runtime.h>
#include <math.h>

#define NB 16
#define NT 100
#define NW 132
#define HID 100
#define FEAT 17424   /* 132*132 */

// ---------------- static scratch ----------------
__device__ float g_xT[(size_t)NB * NW * NT * 176];   // [b][w][i][176] tf32-rounded, h>=159 zero
__device__ float g_gi[(size_t)NB * NT * FEAT];       // [b][t][feat]  tf32-rounded
__device__ float g_wa[100 * 100 * 19];               // W2∘W1  [p][i][k]
__device__ float g_wtf[100 * 32 * 128];              // W3∘W2∘W1 [i][k(32)][o(128)] tf32, padded
__device__ float g_s2[100];
__device__ float g_bc[100];
__device__ float g_xw[(size_t)NB * NT * 300];        // GRU input proj
__device__ float g_h [(size_t)NB * NT * HID];        // GRU outputs

// ---------------- helpers ----------------
__device__ __forceinline__ unsigned tf32r(float x) {
    unsigned r;
    asm("cvt.rna.tf32.f32 %0, %1;" : "=r"(r) : "f"(x));
    return r;
}
__device__ __forceinline__ float tf32f(float x) { return __uint_as_float(tf32r(x)); }

#define MMA_TF32(cc, a, b0, b1)                                              \
    asm volatile("mma.sync.aligned.m16n8k8.row.col.f32.tf32.tf32.f32 "       \
        "{%0,%1,%2,%3}, {%4,%5,%6,%7}, {%8,%9}, {%0,%1,%2,%3};"              \
        : "+f"(cc[0]), "+f"(cc[1]), "+f"(cc[2]), "+f"(cc[3])                 \
        : "r"(a[0]), "r"(a[1]), "r"(a[2]), "r"(a[3]), "r"(b0), "r"(b1))

// ---------------- zero-fill padded weight buffer ----------------
__global__ void zfill_k()
{
    float4* p = (float4*)g_wtf;
    int base = blockIdx.x * 1024 + threadIdx.x;   // 100 blocks * 1024 f4
#pragma unroll
    for (int r = 0; r < 4; r++) {
        int j = base + r * 256;
        if (j < 102400) p[j] = make_float4(0.f, 0.f, 0.f, 0.f);
    }
}

// ---------------- weight composition ----------------
// Wa[p,i,kap] = sum_m sum_{k1} W2[p,m,kap-k1] * W1[m,i,k1]
__global__ void compose1_k(const float* __restrict__ w2, const float* __restrict__ w1)
{
    __shared__ float w2s[1000];
    const int p = blockIdx.x;
    for (int j = threadIdx.x; j < 1000; j += 256) w2s[j] = w2[p * 1000 + j];
    __syncthreads();
    for (int idx = threadIdx.x; idx < 1900; idx += 256) {
        int i = idx / 19, kap = idx % 19;
        int k1lo = kap - 9 > 0 ? kap - 9 : 0;
        int k1hi = kap < 9 ? kap : 9;
        float acc = 0.f;
        for (int m = 0; m < 100; m++) {
            const float* w1r = w1 + (m * 100 + i) * 10;
            const float* w2r = w2s + m * 10;
            for (int k1 = k1lo; k1 <= k1hi; k1++)
                acc += w2r[kap - k1] * w1r[k1];
        }
        g_wa[(p * 100 + i) * 19 + kap] = acc;
    }
}

// Wc[o,i,kap] = sum_m sum_{k3} W3[o,m,k3] * Wa[m,i,kap-k3]; stored [i][k][o] tf32
__global__ void compose2_k(const float* __restrict__ w3)
{
    __shared__ float w3s[1000];
    const int o = blockIdx.x;
    for (int j = threadIdx.x; j < 1000; j += 256) w3s[j] = w3[o * 1000 + j];
    __syncthreads();
    for (int idx = threadIdx.x; idx < 2800; idx += 256) {
        int i = idx / 28, kap = idx % 28;
        int k3lo = kap - 18 > 0 ? kap - 18 : 0;
        int k3hi = kap < 9 ? kap : 9;
        float acc = 0.f;
        for (int m = 0; m < 100; m++) {
            const float* war = g_wa + (m * 100 + i) * 19;
            const float* w3r = w3s + m * 10;
            for (int k3 = k3lo; k3 <= k3hi; k3++)
                acc += w3r[k3] * war[kap - k3];
        }
        g_wtf[(i * 32 + kap) * 128 + o] = __uint_as_float(tf32r(acc));
    }
}

// ---------------- bias composition ----------------
__global__ void bias1_k(const float* __restrict__ w2, const float* __restrict__ b1,
                        const float* __restrict__ b2)
{
    __shared__ float red[128];
    const int t = blockIdx.x, tid = threadIdx.x;
    float p = 0.f;
    for (int m = tid; m < 100; m += 128) {
        const float* r = w2 + (t * 100 + m) * 10;
        float ws = 0.f;
#pragma unroll
        for (int k = 0; k < 10; k++) ws += r[k];
        p += ws * b1[m];
    }
    red[tid] = p; __syncthreads();
    for (int s = 64; s > 0; s >>= 1) { if (tid < s) red[tid] += red[tid + s]; __syncthreads(); }
    if (tid == 0) g_s2[t] = red[0] + b2[t];
}
__global__ void bias2_k(const float* __restrict__ w3, const float* __restrict__ b3)
{
    __shared__ float red[128];
    const int t = blockIdx.x, tid = threadIdx.x;
    float p = 0.f;
    for (int m = tid; m < 100; m += 128) {
        const float* r = w3 + (t * 100 + m) * 10;
        float ws = 0.f;
#pragma unroll
        for (int k = 0; k < 10; k++) ws += r[k];
        p += ws * g_s2[m];
    }
    red[tid] = p; __syncthreads();
    for (int s = 64; s > 0; s >>= 1) { if (tid < s) red[tid] += red[tid + s]; __syncthreads(); }
    if (tid == 0) g_bc[t] = red[0] + b3[t];
}

// ---------------- x: [b][i][h][w] -> [b][w][i][176] tf32, zero tail --------
__global__ void transpose_x_k(const float* __restrict__ x)
{
    __shared__ float s[32][33];
    int plane = blockIdx.x;               // b*100 + i
    int b = plane / 100, i = plane % 100;
    int h0 = blockIdx.y * 32, w0 = blockIdx.z * 32;
    int tx = threadIdx.x, ty = threadIdx.y;
    const float* xp = x + (size_t)plane * (159 * 132);
#pragma unroll
    for (int j = 0; j < 4; j++) {
        int h = h0 + ty + j * 8, w = w0 + tx;
        s[ty + j * 8][tx] = (h < 159 && w < 132) ? xp[h * 132 + w] : 0.f;
    }
    __syncthreads();
#pragma unroll
    for (int j = 0; j < 4; j++) {
        int w = w0 + ty + j * 8, h = h0 + tx;
        if (w < 132 && h < 176)
            g_xT[((size_t)(b * 132 + w) * 100 + i) * 176 + h] = tf32f(s[tx][ty + j * 8]);
    }
}

// ---------------- composite conv as tf32 MMA --------------------------------
// per CTA: one (b,w).  C[o=128][h=144] = Wc[128][3200] x Hankel(xs)[3200][144]
// writes valid (o<100, h<132) directly into g_gi[b][t=o][h*132+w]
__global__ void __launch_bounds__(256, 2)
convmma_k()
{
    extern __shared__ float sm[];
    float* xs = sm;                 // 100*176 = 17600
    float* ws = sm + 17600;         // 2 * 32*128 = 8192
    const int bw = blockIdx.x;
    const int b = bw / 132, w = bw % 132;
    const int tid = threadIdx.x;
    const int lane = tid & 31, warp = tid >> 5;
    const int gID = lane >> 2, tig = lane & 3;
    const int m0 = (warp >> 1) * 32;      // o base for warp
    const int n0 = (warp & 1) * 72;       // h base for warp

    // load slab (already tf32-rounded)
    {
        const float4* inp4 = (const float4*)(g_xT + (size_t)bw * 17600);
        float4* xs4 = (float4*)xs;
        for (int j = tid; j < 4400; j += 256) xs4[j] = inp4[j];
    }

    const float4* wg4 = (const float4*)g_wtf;
    float4 stage[4];
#pragma unroll
    for (int r = 0; r < 4; r++) stage[r] = wg4[tid + 256 * r];   // chunk 0
    // store chunk 0 into buf 0 with XOR swizzle
#pragma unroll
    for (int r = 0; r < 4; r++) {
        int v = tid + 256 * r;
        int k = v >> 5, o = (v & 31) << 2;
        int osw = o ^ ((k & 3) << 3);
        *(float4*)&ws[k * 128 + osw] = stage[r];
    }

    float c[2][9][4];
#pragma unroll
    for (int mt = 0; mt < 2; mt++)
#pragma unroll
        for (int nt = 0; nt < 9; nt++)
#pragma unroll
            for (int q = 0; q < 4; q++) c[mt][nt][q] = 0.f;

    for (int i = 0; i < 100; i++) {
        __syncthreads();
        if (i + 1 < 100) {
#pragma unroll
            for (int r = 0; r < 4; r++)
                stage[r] = wg4[(size_t)(i + 1) * 1024 + tid + 256 * r];
        }
        const float* xrow = xs + i * 176 + n0;
        const unsigned* wsb = (const unsigned*)(ws + (i & 1) * 4096);
#pragma unroll
        for (int kc = 0; kc < 4; kc++) {
            unsigned a[2][4];
#pragma unroll
            for (int mt = 0; mt < 2; mt++) {
                int row = m0 + mt * 16 + gID;
                int xr = tig << 3;
                a[mt][0] = wsb[(kc * 8 + tig) * 128 + (row ^ xr)];
                a[mt][1] = wsb[(kc * 8 + tig) * 128 + ((row + 8) ^ xr)];
                a[mt][2] = wsb[(kc * 8 + tig + 4) * 128 + (row ^ xr)];
                a[mt][3] = wsb[(kc * 8 + tig + 4) * 128 + ((row + 8) ^ xr)];
            }
            const float* bbase = xrow + kc * 8 + gID + tig;
#pragma unroll
            for (int nt = 0; nt < 9; nt++) {
                unsigned b0 = __float_as_uint(bbase[nt * 8]);
                unsigned b1 = __float_as_uint(bbase[nt * 8 + 4]);
                MMA_TF32(c[0][nt], a[0], b0, b1);
                MMA_TF32(c[1][nt], a[1], b0, b1);
            }
        }
        if (i + 1 < 100) {
#pragma unroll
            for (int r = 0; r < 4; r++) {
                int v = tid + 256 * r;
                int k = v >> 5, o = (v & 31) << 2;
                int osw = o ^ ((k & 3) << 3);
                *(float4*)&ws[((i + 1) & 1) * 4096 + k * 128 + osw] = stage[r];
            }
        }
    }

    // epilogue: +bias, tf32-round, scatter into gi layout
    const int bb = b * 100;
#pragma unroll
    for (int mt = 0; mt < 2; mt++) {
        int o_lo = m0 + mt * 16 + gID;
        int o_hi = o_lo + 8;
        float blo = (o_lo < 100) ? g_bc[o_lo] : 0.f;
        float bhi = (o_hi < 100) ? g_bc[o_hi] : 0.f;
        float* glo = g_gi + (size_t)(bb + o_lo) * FEAT + w;
        float* ghi = g_gi + (size_t)(bb + o_hi) * FEAT + w;
#pragma unroll
        for (int nt = 0; nt < 9; nt++) {
            int h = n0 + nt * 8 + 2 * tig;
            if (o_lo < 100) {
                if (h < 132)     glo[h * 132]       = tf32f(c[mt][nt][0] + blo);
                if (h + 1 < 132) glo[(h + 1) * 132] = tf32f(c[mt][nt][1] + blo);
            }
            if (o_hi < 100) {
                if (h < 132)     ghi[h * 132]       = tf32f(c[mt][nt][2] + bhi);
                if (h + 1 < 132) ghi[(h + 1) * 132] = tf32f(c[mt][nt][3] + bhi);
            }
        }
    }
}

// ---------------- GRU input projection via tf32 MMA -------------------------
// C[1600,300] = gi[1600,17424] x w_ih[300,17424]^T
__global__ void __launch_bounds__(256, 2)
gemmxw_k(const float* __restrict__ w_ih)
{
    __shared__ float As[2][128 * 28];
    __shared__ float Bs[2][80 * 28];
    const int m0 = blockIdx.x * 128;
    const int n0 = blockIdx.y * 80;
    const int tid = threadIdx.x, lane = tid & 31, warp = tid >> 5;
    const int gID = lane >> 2, tig = lane & 3;
    const int m0w = (warp >> 1) * 32;
    const int n0w = (warp & 1) * 40;

    float c[2][5][4];
#pragma unroll
    for (int mt = 0; mt < 2; mt++)
#pragma unroll
        for (int nt = 0; nt < 5; nt++)
#pragma unroll
            for (int q = 0; q < 4; q++) c[mt][nt][q] = 0.f;

    // load iteration 0 into buf 0
#pragma unroll
    for (int r = 0; r < 3; r++) {
        int j = tid + 256 * r;
        int row = j / 6, c4 = j % 6;
        float4 v = make_float4(0.f, 0.f, 0.f, 0.f);
        if (m0 + row < 1600) v = *(const float4*)(g_gi + (size_t)(m0 + row) * FEAT + c4 * 4);
        *(float4*)&As[0][row * 28 + c4 * 4] = v;
    }
#pragma unroll
    for (int r = 0; r < 2; r++) {
        int j = tid + 256 * r;
        if (j < 480) {
            int row = j / 6, c4 = j % 6;
            float4 v = make_float4(0.f, 0.f, 0.f, 0.f);
            if (n0 + row < 300) v = *(const float4*)(w_ih + (size_t)(n0 + row) * FEAT + c4 * 4);
            v.x = tf32f(v.x); v.y = tf32f(v.y); v.z = tf32f(v.z); v.w = tf32f(v.w);
            *(float4*)&Bs[0][row * 28 + c4 * 4] = v;
        }
    }
    __syncthreads();

    for (int it = 0; it < 726; it++) {
        if (it + 1 < 726) {
            const int kk = (it + 1) * 24;
            const int nb = (it + 1) & 1;
#pragma unroll
            for (int r = 0; r < 3; r++) {
                int j = tid + 256 * r;
                int row = j / 6, c4 = j % 6;
                float4 v = make_float4(0.f, 0.f, 0.f, 0.f);
                if (m0 + row < 1600) v = *(const float4*)(g_gi + (size_t)(m0 + row) * FEAT + kk + c4 * 4);
                *(float4*)&As[nb][row * 28 + c4 * 4] = v;
            }
#pragma unroll
            for (int r = 0; r < 2; r++) {
                int j = tid + 256 * r;
                if (j < 480) {
                    int row = j / 6, c4 = j % 6;
                    float4 v = make_float4(0.f, 0.f, 0.f, 0.f);
                    if (n0 + row < 300) v = *(const float4*)(w_ih + (size_t)(n0 + row) * FEAT + kk + c4 * 4);
                    v.x = tf32f(v.x); v.y = tf32f(v.y); v.z = tf32f(v.z); v.w = tf32f(v.w);
                    *(float4*)&Bs[nb][row * 28 + c4 * 4] = v;
                }
            }
        }
        const unsigned* Ab = (const unsigned*)As[it & 1];
        const unsigned* Bb = (const unsigned*)Bs[it & 1];
#pragma unroll
        for (int kc = 0; kc < 3; kc++) {
            unsigned a[2][4];
#pragma unroll
            for (int mt = 0; mt < 2; mt++) {
                int row = m0w + mt * 16 + gID;
                a[mt][0] = Ab[row * 28 + kc * 8 + tig];
                a[mt][1] = Ab[(row + 8) * 28 + kc * 8 + tig];
                a[mt][2] = Ab[row * 28 + kc * 8 + tig + 4];
                a[mt][3] = Ab[(row + 8) * 28 + kc * 8 + tig + 4];
            }
#pragma unroll
            for (int nt = 0; nt < 5; nt++) {
                int nrow = n0w + nt * 8 + gID;
                unsigned b0 = Bb[nrow * 28 + kc * 8 + tig];
                unsigned b1 = Bb[nrow * 28 + kc * 8 + tig + 4];
                MMA_TF32(c[0][nt], a[0], b0, b1);
                MMA_TF32(c[1][nt], a[1], b0, b1);
            }
        }
        __syncthreads();
    }

#pragma unroll
    for (int mt = 0; mt < 2; mt++) {
        int m_lo = m0 + m0w + mt * 16 + gID;
        int m_hi = m_lo + 8;
#pragma unroll
        for (int nt = 0; nt < 5; nt++) {
            int n = n0 + n0w + nt * 8 + 2 * tig;
            if (m_lo < 1600) {
                if (n < 300)     g_xw[(size_t)m_lo * 300 + n]     = c[mt][nt][0];
                if (n + 1 < 300) g_xw[(size_t)m_lo * 300 + n + 1] = c[mt][nt][1];
            }
            if (m_hi < 1600) {
                if (n < 300)     g_xw[(size_t)m_hi * 300 + n]     = c[mt][nt][2];
                if (n + 1 < 300) g_xw[(size_t)m_hi * 300 + n + 1] = c[mt][nt][3];
            }
        }
    }
}

// ---------------- GRU recurrence ----------------
__global__ void __launch_bounds__(320)
gru_k(const float* __restrict__ w_hh, const float* __restrict__ b_ih,
      const float* __restrict__ b_hh)
{
    const int b = blockIdx.x;
    const int g = threadIdx.x;
    __shared__ float h_s[104];
    __shared__ float gh_s[300];
    __shared__ float xw_s[300];

    float wreg[100];
    float bih = 0.f, bhh = 0.f;
    if (g < 300) {
        bih = b_ih[g];
        bhh = b_hh[g];
#pragma unroll
        for (int j = 0; j < 100; j++) wreg[j] = w_hh[g * 100 + j];
    }
    if (g < 104) h_s[g] = 0.f;
    __syncthreads();

    const float* xwp = g_xw + (size_t)b * 100 * 300;
    for (int t = 0; t < 100; t++) {
        if (g < 300) {
            float xv = xwp[t * 300 + g] + bih;
            float acc = bhh;
#pragma unroll
            for (int j4 = 0; j4 < 25; j4++) {
                float4 hv = *(const float4*)&h_s[j4 * 4];
                acc += wreg[j4 * 4 + 0] * hv.x;
                acc += wreg[j4 * 4 + 1] * hv.y;
                acc += wreg[j4 * 4 + 2] * hv.z;
                acc += wreg[j4 * 4 + 3] * hv.w;
            }
            gh_s[g] = acc;
            xw_s[g] = xv;
        }
        __syncthreads();
        if (g < 100) {
            float r = 1.f / (1.f + expf(-(xw_s[g] + gh_s[g])));
            float z = 1.f / (1.f + expf(-(xw_s[100 + g] + gh_s[100 + g])));
            float n = tanhf(xw_s[200 + g] + r * gh_s[200 + g]);
            float hn = (1.f - z) * n + z * h_s[g];
            h_s[g] = hn;
            g_h[((size_t)b * 100 + t) * 100 + g] = hn;
        }
        __syncthreads();
    }
}

// ---------------- output heads ----------------
__global__ void heads_k(const float* __restrict__ wy1, const float* __restrict__ by1,
                        const float* __restrict__ wy2, const float* __restrict__ by2,
                        float* __restrict__ out)
{
    int idx = blockIdx.x * blockDim.x + threadIdx.x;
    if (idx >= 1600 * 17) return;
    int bt = idx / 17, c = idx - bt * 17;
    const float* gv = g_h + (size_t)bt * 100;
    if (c < 14) {
        const float* wv = wy1 + c * 100;
        float acc = by1[c];
#pragma unroll 4
        for (int j = 0; j < 100; j++) acc += gv[j] * wv[j];
        out[bt * 14 + c] = 1.f / (1.f + expf(-acc));
    } else {
        int c2 = c - 14;
        const float* wv = wy2 + c2 * 100;
        float acc = by2[c2];
#pragma unroll 4
        for (int j = 0; j < 100; j++) acc += gv[j] * wv[j];
        out[1600 * 14 + bt * 3 + c2] = tanhf(acc) * 10.f;
    }
}

// ---------------- launch ----------------
extern "C" void kernel_launch(void* const* d_in, const int* in_sizes, int n_in,
                              void* d_out, int out_size)
{
    (void)in_sizes; (void)n_in; (void)out_size;
    const float* x    = (const float*)d_in[0];
    const float* w1   = (const float*)d_in[1];
    const float* bc1  = (const float*)d_in[2];
    const float* w2   = (const float*)d_in[3];
    const float* bc2  = (const float*)d_in[4];
    const float* w3   = (const float*)d_in[5];
    const float* bc3  = (const float*)d_in[6];
    const float* w_ih = (const float*)d_in[7];
    const float* w_hh = (const float*)d_in[8];
    const float* b_ih = (const float*)d_in[9];
    const float* b_hh = (const float*)d_in[10];
    const float* w_y1 = (const float*)d_in[11];
    const float* b_y1 = (const float*)d_in[12];
    const float* w_y2 = (const float*)d_in[13];
    const float* b_y2 = (const float*)d_in[14];
    float* out = (float*)d_out;

    const int conv_smem = (17600 + 8192) * 4;   // 103168 B
    cudaFuncSetAttribute(convmma_k, cudaFuncAttributeMaxDynamicSharedMemorySize, conv_smem);

    zfill_k<<<100, 256>>>();
    compose1_k<<<100, 256>>>(w2, w1);
    compose2_k<<<100, 256>>>(w3);
    bias1_k<<<100, 128>>>(w2, bc1, bc2);
    bias2_k<<<100, 128>>>(w3, bc3);
    transpose_x_k<<<dim3(1600, 6, 5), dim3(32, 8)>>>(x);
    convmma_k<<<NB * NW, 256, conv_smem>>>();
    gemmxw_k<<<dim3(13, 4), 256>>>(w_ih);
    gru_k<<<16, 320>>>(w_hh, b_ih, b_hh);
    heads_k<<<(1600 * 17 + 255) / 256, 256>>>(w_y1, b_y1, w_y2, b_y2, out);
}

// round 4
// speedup vs baseline: 1.5649x; 1.0004x over previous
#include <cuda_runtime.h>
#include <math.h>

#define NB 16
#define NT 100
#define NW 132
#define HID 100
#define FEAT 17424   /* 132*132 */

// ---------------- static scratch ----------------
__device__ float g_xT[(size_t)NB * NW * NT * 176];   // [b][w][i][176] tf32-rounded, h>=159 zero
__device__ float g_gi[(size_t)NB * NT * FEAT];       // [b][t][feat]  tf32-rounded
__device__ float g_wa[100 * 100 * 19];               // W2∘W1  [p][i][k]
__device__ float g_wtf[100 * 32 * 128];              // W3∘W2∘W1 [i][k(32)][o(128)] tf32, padded
__device__ float g_s2[100];
__device__ float g_bc[100];
__device__ float g_xw[(size_t)NB * NT * 300];        // GRU input proj
__device__ float g_h [(size_t)NB * NT * HID];        // GRU outputs

// ---------------- helpers ----------------
__device__ __forceinline__ unsigned tf32r(float x) {
    unsigned r;
    asm("cvt.rna.tf32.f32 %0, %1;" : "=r"(r) : "f"(x));
    return r;
}
__device__ __forceinline__ float tf32f(float x) { return __uint_as_float(tf32r(x)); }

#define MMA_TF32(cc, a, b0, b1)                                              \
    asm volatile("mma.sync.aligned.m16n8k8.row.col.f32.tf32.tf32.f32 "       \
        "{%0,%1,%2,%3}, {%4,%5,%6,%7}, {%8,%9}, {%0,%1,%2,%3};"              \
        : "+f"(cc[0]), "+f"(cc[1]), "+f"(cc[2]), "+f"(cc[3])                 \
        : "r"(a[0]), "r"(a[1]), "r"(a[2]), "r"(a[3]), "r"(b0), "r"(b1))

// ---------------- zero-fill padded weight buffer ----------------
__global__ void zfill_k()
{
    float4* p = (float4*)g_wtf;
    int base = blockIdx.x * 1024 + threadIdx.x;   // 100 blocks * 1024 f4
#pragma unroll
    for (int r = 0; r < 4; r++) {
        int j = base + r * 256;
        if (j < 102400) p[j] = make_float4(0.f, 0.f, 0.f, 0.f);
    }
}

// ---------------- weight composition ----------------
// Wa[p,i,kap] = sum_m sum_{k1} W2[p,m,kap-k1] * W1[m,i,k1]
__global__ void compose1_k(const float* __restrict__ w2, const float* __restrict__ w1)
{
    __shared__ float w2s[1000];
    const int p = blockIdx.x;
    for (int j = threadIdx.x; j < 1000; j += 256) w2s[j] = w2[p * 1000 + j];
    __syncthreads();
    for (int idx = threadIdx.x; idx < 1900; idx += 256) {
        int i = idx / 19, kap = idx % 19;
        int k1lo = kap - 9 > 0 ? kap - 9 : 0;
        int k1hi = kap < 9 ? kap : 9;
        float acc = 0.f;
        for (int m = 0; m < 100; m++) {
            const float* w1r = w1 + (m * 100 + i) * 10;
            const float* w2r = w2s + m * 10;
            for (int k1 = k1lo; k1 <= k1hi; k1++)
                acc += w2r[kap - k1] * w1r[k1];
        }
        g_wa[(p * 100 + i) * 19 + kap] = acc;
    }
}

// Wc[o,i,kap] = sum_m sum_{k3} W3[o,m,k3] * Wa[m,i,kap-k3]; stored [i][k][o] tf32
__global__ void compose2_k(const float* __restrict__ w3)
{
    __shared__ float w3s[1000];
    const int o = blockIdx.x;
    for (int j = threadIdx.x; j < 1000; j += 256) w3s[j] = w3[o * 1000 + j];
    __syncthreads();
    for (int idx = threadIdx.x; idx < 2800; idx += 256) {
        int i = idx / 28, kap = idx % 28;
        int k3lo = kap - 18 > 0 ? kap - 18 : 0;
        int k3hi = kap < 9 ? kap : 9;
        float acc = 0.f;
        for (int m = 0; m < 100; m++) {
            const float* war = g_wa + (m * 100 + i) * 19;
            const float* w3r = w3s + m * 10;
            for (int k3 = k3lo; k3 <= k3hi; k3++)
                acc += w3r[k3] * war[kap - k3];
        }
        g_wtf[(i * 32 + kap) * 128 + o] = __uint_as_float(tf32r(acc));
    }
}

// ---------------- bias composition ----------------
__global__ void bias1_k(const float* __restrict__ w2, const float* __restrict__ b1,
                        const float* __restrict__ b2)
{
    __shared__ float red[128];
    const int t = blockIdx.x, tid = threadIdx.x;
    float p = 0.f;
    for (int m = tid; m < 100; m += 128) {
        const float* r = w2 + (t * 100 + m) * 10;
        float ws = 0.f;
#pragma unroll
        for (int k = 0; k < 10; k++) ws += r[k];
        p += ws * b1[m];
    }
    red[tid] = p; __syncthreads();
    for (int s = 64; s > 0; s >>= 1) { if (tid < s) red[tid] += red[tid + s]; __syncthreads(); }
    if (tid == 0) g_s2[t] = red[0] + b2[t];
}
__global__ void bias2_k(const float* __restrict__ w3, const float* __restrict__ b3)
{
    __shared__ float red[128];
    const int t = blockIdx.x, tid = threadIdx.x;
    float p = 0.f;
    for (int m = tid; m < 100; m += 128) {
        const float* r = w3 + (t * 100 + m) * 10;
        float ws = 0.f;
#pragma unroll
        for (int k = 0; k < 10; k++) ws += r[k];
        p += ws * g_s2[m];
    }
    red[tid] = p; __syncthreads();
    for (int s = 64; s > 0; s >>= 1) { if (tid < s) red[tid] += red[tid + s]; __syncthreads(); }
    if (tid == 0) g_bc[t] = red[0] + b3[t];
}

// ---------------- x: [b][i][h][w] -> [b][w][i][176] tf32, zero tail --------
__global__ void transpose_x_k(const float* __restrict__ x)
{
    __shared__ float s[32][33];
    int plane = blockIdx.x;               // b*100 + i
    int b = plane / 100, i = plane % 100;
    int h0 = blockIdx.y * 32, w0 = blockIdx.z * 32;
    int tx = threadIdx.x, ty = threadIdx.y;
    const float* xp = x + (size_t)plane * (159 * 132);
#pragma unroll
    for (int j = 0; j < 4; j++) {
        int h = h0 + ty + j * 8, w = w0 + tx;
        s[ty + j * 8][tx] = (h < 159 && w < 132) ? xp[h * 132 + w] : 0.f;
    }
    __syncthreads();
#pragma unroll
    for (int j = 0; j < 4; j++) {
        int w = w0 + ty + j * 8, h = h0 + tx;
        if (w < 132 && h < 176)
            g_xT[((size_t)(b * 132 + w) * 100 + i) * 176 + h] = tf32f(s[tx][ty + j * 8]);
    }
}

// ---------------- composite conv as tf32 MMA --------------------------------
// per CTA: one (b,w).  C[o=128][h=144] = Wc[128][3200] x Hankel(xs)[3200][144]
// writes valid (o<100, h<132) directly into g_gi[b][t=o][h*132+w]
__global__ void __launch_bounds__(256, 2)
convmma_k()
{
    extern __shared__ float sm[];
    float* xs = sm;                 // 100*176 = 17600
    float* ws = sm + 17600;         // 2 * 32*128 = 8192
    const int bw = blockIdx.x;
    const int b = bw / 132, w = bw % 132;
    const int tid = threadIdx.x;
    const int lane = tid & 31, warp = tid >> 5;
    const int gID = lane >> 2, tig = lane & 3;
    const int m0 = (warp >> 1) * 32;      // o base for warp
    const int n0 = (warp & 1) * 72;       // h base for warp

    // load slab (already tf32-rounded)
    {
        const float4* inp4 = (const float4*)(g_xT + (size_t)bw * 17600);
        float4* xs4 = (float4*)xs;
        for (int j = tid; j < 4400; j += 256) xs4[j] = inp4[j];
    }

    const float4* wg4 = (const float4*)g_wtf;
    float4 stage[4];
#pragma unroll
    for (int r = 0; r < 4; r++) stage[r] = wg4[tid + 256 * r];   // chunk 0
    // store chunk 0 into buf 0 with XOR swizzle
#pragma unroll
    for (int r = 0; r < 4; r++) {
        int v = tid + 256 * r;
        int k = v >> 5, o = (v & 31) << 2;
        int osw = o ^ ((k & 3) << 3);
        *(float4*)&ws[k * 128 + osw] = stage[r];
    }

    float c[2][9][4];
#pragma unroll
    for (int mt = 0; mt < 2; mt++)
#pragma unroll
        for (int nt = 0; nt < 9; nt++)
#pragma unroll
            for (int q = 0; q < 4; q++) c[mt][nt][q] = 0.f;

    for (int i = 0; i < 100; i++) {
        __syncthreads();
        if (i + 1 < 100) {
#pragma unroll
            for (int r = 0; r < 4; r++)
                stage[r] = wg4[(size_t)(i + 1) * 1024 + tid + 256 * r];
        }
        const float* xrow = xs + i * 176 + n0;
        const unsigned* wsb = (const unsigned*)(ws + (i & 1) * 4096);
#pragma unroll
        for (int kc = 0; kc < 4; kc++) {
            unsigned a[2][4];
#pragma unroll
            for (int mt = 0; mt < 2; mt++) {
                int row = m0 + mt * 16 + gID;
                int xr = tig << 3;
                a[mt][0] = wsb[(kc * 8 + tig) * 128 + (row ^ xr)];
                a[mt][1] = wsb[(kc * 8 + tig) * 128 + ((row + 8) ^ xr)];
                a[mt][2] = wsb[(kc * 8 + tig + 4) * 128 + (row ^ xr)];
                a[mt][3] = wsb[(kc * 8 + tig + 4) * 128 + ((row + 8) ^ xr)];
            }
            const float* bbase = xrow + kc * 8 + gID + tig;
#pragma unroll
            for (int nt = 0; nt < 9; nt++) {
                unsigned b0 = __float_as_uint(bbase[nt * 8]);
                unsigned b1 = __float_as_uint(bbase[nt * 8 + 4]);
                MMA_TF32(c[0][nt], a[0], b0, b1);
                MMA_TF32(c[1][nt], a[1], b0, b1);
            }
        }
        if (i + 1 < 100) {
#pragma unroll
            for (int r = 0; r < 4; r++) {
                int v = tid + 256 * r;
                int k = v >> 5, o = (v & 31) << 2;
                int osw = o ^ ((k & 3) << 3);
                *(float4*)&ws[((i + 1) & 1) * 4096 + k * 128 + osw] = stage[r];
            }
        }
    }

    // epilogue: +bias, tf32-round, scatter into gi layout
    const int bb = b * 100;
#pragma unroll
    for (int mt = 0; mt < 2; mt++) {
        int o_lo = m0 + mt * 16 + gID;
        int o_hi = o_lo + 8;
        float blo = (o_lo < 100) ? g_bc[o_lo] : 0.f;
        float bhi = (o_hi < 100) ? g_bc[o_hi] : 0.f;
        float* glo = g_gi + (size_t)(bb + o_lo) * FEAT + w;
        float* ghi = g_gi + (size_t)(bb + o_hi) * FEAT + w;
#pragma unroll
        for (int nt = 0; nt < 9; nt++) {
            int h = n0 + nt * 8 + 2 * tig;
            if (o_lo < 100) {
                if (h < 132)     glo[h * 132]       = tf32f(c[mt][nt][0] + blo);
                if (h + 1 < 132) glo[(h + 1) * 132] = tf32f(c[mt][nt][1] + blo);
            }
            if (o_hi < 100) {
                if (h < 132)     ghi[h * 132]       = tf32f(c[mt][nt][2] + bhi);
                if (h + 1 < 132) ghi[(h + 1) * 132] = tf32f(c[mt][nt][3] + bhi);
            }
        }
    }
}

// ---------------- GRU input projection via tf32 MMA -------------------------
// C[1600,300] = gi[1600,17424] x w_ih[300,17424]^T
__global__ void __launch_bounds__(256, 2)
gemmxw_k(const float* __restrict__ w_ih)
{
    __shared__ float As[2][128 * 28];
    __shared__ float Bs[2][80 * 28];
    const int m0 = blockIdx.x * 128;
    const int n0 = blockIdx.y * 80;
    const int tid = threadIdx.x, lane = tid & 31, warp = tid >> 5;
    const int gID = lane >> 2, tig = lane & 3;
    const int m0w = (warp >> 1) * 32;
    const int n0w = (warp & 1) * 40;

    float c[2][5][4];
#pragma unroll
    for (int mt = 0; mt < 2; mt++)
#pragma unroll
        for (int nt = 0; nt < 5; nt++)
#pragma unroll
            for (int q = 0; q < 4; q++) c[mt][nt][q] = 0.f;

    // load iteration 0 into buf 0
#pragma unroll
    for (int r = 0; r < 3; r++) {
        int j = tid + 256 * r;
        int row = j / 6, c4 = j % 6;
        float4 v = make_float4(0.f, 0.f, 0.f, 0.f);
        if (m0 + row < 1600) v = *(const float4*)(g_gi + (size_t)(m0 + row) * FEAT + c4 * 4);
        *(float4*)&As[0][row * 28 + c4 * 4] = v;
    }
#pragma unroll
    for (int r = 0; r < 2; r++) {
        int j = tid + 256 * r;
        if (j < 480) {
            int row = j / 6, c4 = j % 6;
            float4 v = make_float4(0.f, 0.f, 0.f, 0.f);
            if (n0 + row < 300) v = *(const float4*)(w_ih + (size_t)(n0 + row) * FEAT + c4 * 4);
            v.x = tf32f(v.x); v.y = tf32f(v.y); v.z = tf32f(v.z); v.w = tf32f(v.w);
            *(float4*)&Bs[0][row * 28 + c4 * 4] = v;
        }
    }
    __syncthreads();

    for (int it = 0; it < 726; it++) {
        if (it + 1 < 726) {
            const int kk = (it + 1) * 24;
            const int nb = (it + 1) & 1;
#pragma unroll
            for (int r = 0; r < 3; r++) {
                int j = tid + 256 * r;
                int row = j / 6, c4 = j % 6;
                float4 v = make_float4(0.f, 0.f, 0.f, 0.f);
                if (m0 + row < 1600) v = *(const float4*)(g_gi + (size_t)(m0 + row) * FEAT + kk + c4 * 4);
                *(float4*)&As[nb][row * 28 + c4 * 4] = v;
            }
#pragma unroll
            for (int r = 0; r < 2; r++) {
                int j = tid + 256 * r;
                if (j < 480) {
                    int row = j / 6, c4 = j % 6;
                    float4 v = make_float4(0.f, 0.f, 0.f, 0.f);
                    if (n0 + row < 300) v = *(const float4*)(w_ih + (size_t)(n0 + row) * FEAT + kk + c4 * 4);
                    v.x = tf32f(v.x); v.y = tf32f(v.y); v.z = tf32f(v.z); v.w = tf32f(v.w);
                    *(float4*)&Bs[nb][row * 28 + c4 * 4] = v;
                }
            }
        }
        const unsigned* Ab = (const unsigned*)As[it & 1];
        const unsigned* Bb = (const unsigned*)Bs[it & 1];
#pragma unroll
        for (int kc = 0; kc < 3; kc++) {
            unsigned a[2][4];
#pragma unroll
            for (int mt = 0; mt < 2; mt++) {
                int row = m0w + mt * 16 + gID;
                a[mt][0] = Ab[row * 28 + kc * 8 + tig];
                a[mt][1] = Ab[(row + 8) * 28 + kc * 8 + tig];
                a[mt][2] = Ab[row * 28 + kc * 8 + tig + 4];
                a[mt][3] = Ab[(row + 8) * 28 + kc * 8 + tig + 4];
            }
#pragma unroll
            for (int nt = 0; nt < 5; nt++) {
                int nrow = n0w + nt * 8 + gID;
                unsigned b0 = Bb[nrow * 28 + kc * 8 + tig];
                unsigned b1 = Bb[nrow * 28 + kc * 8 + tig + 4];
                MMA_TF32(c[0][nt], a[0], b0, b1);
                MMA_TF32(c[1][nt], a[1], b0, b1);
            }
        }
        __syncthreads();
    }

#pragma unroll
    for (int mt = 0; mt < 2; mt++) {
        int m_lo = m0 + m0w + mt * 16 + gID;
        int m_hi = m_lo + 8;
#pragma unroll
        for (int nt = 0; nt < 5; nt++) {
            int n = n0 + n0w + nt * 8 + 2 * tig;
            if (m_lo < 1600) {
                if (n < 300)     g_xw[(size_t)m_lo * 300 + n]     = c[mt][nt][0];
                if (n + 1 < 300) g_xw[(size_t)m_lo * 300 + n + 1] = c[mt][nt][1];
            }
            if (m_hi < 1600) {
                if (n < 300)     g_xw[(size_t)m_hi * 300 + n]     = c[mt][nt][2];
                if (n + 1 < 300) g_xw[(size_t)m_hi * 300 + n + 1] = c[mt][nt][3];
            }
        }
    }
}

// ---------------- GRU recurrence ----------------
__global__ void __launch_bounds__(320)
gru_k(const float* __restrict__ w_hh, const float* __restrict__ b_ih,
      const float* __restrict__ b_hh)
{
    const int b = blockIdx.x;
    const int g = threadIdx.x;
    __shared__ float h_s[104];
    __shared__ float gh_s[300];
    __shared__ float xw_s[300];

    float wreg[100];
    float bih = 0.f, bhh = 0.f;
    if (g < 300) {
        bih = b_ih[g];
        bhh = b_hh[g];
#pragma unroll
        for (int j = 0; j < 100; j++) wreg[j] = w_hh[g * 100 + j];
    }
    if (g < 104) h_s[g] = 0.f;
    __syncthreads();

    const float* xwp = g_xw + (size_t)b * 100 * 300;
    for (int t = 0; t < 100; t++) {
        if (g < 300) {
            float xv = xwp[t * 300 + g] + bih;
            float acc = bhh;
#pragma unroll
            for (int j4 = 0; j4 < 25; j4++) {
                float4 hv = *(const float4*)&h_s[j4 * 4];
                acc += wreg[j4 * 4 + 0] * hv.x;
                acc += wreg[j4 * 4 + 1] * hv.y;
                acc += wreg[j4 * 4 + 2] * hv.z;
                acc += wreg[j4 * 4 + 3] * hv.w;
            }
            gh_s[g] = acc;
            xw_s[g] = xv;
        }
        __syncthreads();
        if (g < 100) {
            float r = 1.f / (1.f + expf(-(xw_s[g] + gh_s[g])));
            float z = 1.f / (1.f + expf(-(xw_s[100 + g] + gh_s[100 + g])));
            float n = tanhf(xw_s[200 + g] + r * gh_s[200 + g]);
            float hn = (1.f - z) * n + z * h_s[g];
            h_s[g] = hn;
            g_h[((size_t)b * 100 + t) * 100 + g] = hn;
        }
        __syncthreads();
    }
}

// ---------------- output heads ----------------
__global__ void heads_k(const float* __restrict__ wy1, const float* __restrict__ by1,
                        const float* __restrict__ wy2, const float* __restrict__ by2,
                        float* __restrict__ out)
{
    int idx = blockIdx.x * blockDim.x + threadIdx.x;
    if (idx >= 1600 * 17) return;
    int bt = idx / 17, c = idx - bt * 17;
    const float* gv = g_h + (size_t)bt * 100;
    if (c < 14) {
        const float* wv = wy1 + c * 100;
        float acc = by1[c];
#pragma unroll 4
        for (int j = 0; j < 100; j++) acc += gv[j] * wv[j];
        out[bt * 14 + c] = 1.f / (1.f + expf(-acc));
    } else {
        int c2 = c - 14;
        const float* wv = wy2 + c2 * 100;
        float acc = by2[c2];
#pragma unroll 4
        for (int j = 0; j < 100; j++) acc += gv[j] * wv[j];
        out[1600 * 14 + bt * 3 + c2] = tanhf(acc) * 10.f;
    }
}

// ---------------- launch ----------------
extern "C" void kernel_launch(void* const* d_in, const int* in_sizes, int n_in,
                              void* d_out, int out_size)
{
    (void)in_sizes; (void)n_in; (void)out_size;
    const float* x    = (const float*)d_in[0];
    const float* w1   = (const float*)d_in[1];
    const float* bc1  = (const float*)d_in[2];
    const float* w2   = (const float*)d_in[3];
    const float* bc2  = (const float*)d_in[4];
    const float* w3   = (const float*)d_in[5];
    const float* bc3  = (const float*)d_in[6];
    const float* w_ih = (const float*)d_in[7];
    const float* w_hh = (const float*)d_in[8];
    const float* b_ih = (const float*)d_in[9];
    const float* b_hh = (const float*)d_in[10];
    const float* w_y1 = (const float*)d_in[11];
    const float* b_y1 = (const float*)d_in[12];
    const float* w_y2 = (const float*)d_in[13];
    const float* b_y2 = (const float*)d_in[14];
    float* out = (float*)d_out;

    const int conv_smem = (17600 + 8192) * 4;   // 103168 B
    cudaFuncSetAttribute(convmma_k, cudaFuncAttributeMaxDynamicSharedMemorySize, conv_smem);

    zfill_k<<<100, 256>>>();
    compose1_k<<<100, 256>>>(w2, w1);
    compose2_k<<<100, 256>>>(w3);
    bias1_k<<<100, 128>>>(w2, bc1, bc2);
    bias2_k<<<100, 128>>>(w3, bc3);
    transpose_x_k<<<dim3(1600, 6, 5), dim3(32, 8)>>>(x);
    convmma_k<<<NB * NW, 256, conv_smem>>>();
    gemmxw_k<<<dim3(13, 4), 256>>>(w_ih);
    gru_k<<<16, 320>>>(w_hh, b_ih, b_hh);
    heads_k<<<(1600 * 17 + 255) / 256, 256>>>(w_y1, b_y1, w_y2, b_y2, out);
}